// round 16
// baseline (speedup 1.0000x reference)
#include <cuda_runtime.h>
#include <cuda_bf16.h>
#include <math.h>
#include <stdint.h>

// SlotAttention GB300 — Round 14: single fp32 x̂ array (R10 memory behavior)
// + HMMA phase-1 logits with ON-THE-FLY bf16 hi/lo conversion during smem
// staging (fixes R11's extra-DRAM failure). Phase 2 & slot chain = R10 exact.

#define Bb 64
#define Nn 4096
#define Dd 256
#define Kk 15
#define Hh 512
#define BN_TOT (Bb * Nn)   // 262144
#define BK_TOT (Bb * Kk)   // 960
#define NCH 32             // n-chunks per batch
#define CHN 128            // n per chunk (HMMA tile M)
#define SROW 72            // x̂ smem row stride (bf16)
#define QROW 264           // q smem row stride (bf16)
#define AS2 132            // attn smem row stride (floats)

// dynamic smem byte offsets for attn_pass
#define SM_XH 0
#define SM_XL 18432
#define SM_QH 36864
#define SM_QL 45312
#define SM_AS 53760
#define SM_BYTES 61680

// ---------------- scratch ----------------
__device__ float g_xln[(size_t)BN_TOT * Dd];      // 256 MiB (ONLY x̂ copy)
__device__ float g_wqk[Dd * Dd];
__device__ float g_wiv[3 * Dd * Dd];
__device__ float g_slots[BK_TOT * Dd];
__device__ float g_q[BK_TOT * Dd];
__device__ float g_part[BK_TOT * NCH];
__device__ float g_updpart[(size_t)NCH * BK_TOT * Dd];  // 31.5 MB

// ---------------- helpers ----------------
__device__ __forceinline__ float warp_sum(float v) {
#pragma unroll
    for (int o = 16; o > 0; o >>= 1) v += __shfl_xor_sync(0xffffffffu, v, o);
    return v;
}
__device__ __forceinline__ float sigmoidf_(float x) { return 1.0f / (1.0f + __expf(-x)); }

__device__ __forceinline__ uint32_t smem_u32(const void* p) {
    uint32_t a;
    asm("{ .reg .u64 t; cvta.to.shared.u64 t, %1; cvt.u32.u64 %0, t; }" : "=r"(a) : "l"(p));
    return a;
}
__device__ __forceinline__ void ldsm_x4(uint32_t& r0, uint32_t& r1, uint32_t& r2, uint32_t& r3,
                                        uint32_t addr) {
    asm volatile("ldmatrix.sync.aligned.m8n8.x4.shared.b16 {%0,%1,%2,%3}, [%4];"
                 : "=r"(r0), "=r"(r1), "=r"(r2), "=r"(r3) : "r"(addr));
}
__device__ __forceinline__ void mma_bf16(float* c, uint32_t a0, uint32_t a1, uint32_t a2,
                                         uint32_t a3, uint32_t b0, uint32_t b1) {
    asm volatile(
        "mma.sync.aligned.m16n8k16.row.col.f32.bf16.bf16.f32 "
        "{%0,%1,%2,%3}, {%4,%5,%6,%7}, {%8,%9}, {%0,%1,%2,%3};"
        : "+f"(c[0]), "+f"(c[1]), "+f"(c[2]), "+f"(c[3])
        : "r"(a0), "r"(a1), "r"(a2), "r"(a3), "r"(b0), "r"(b1));
}

// split a float4 into packed hi (bf16x2 pair) and lo
__device__ __forceinline__ void split4(float4 v, uint2& hval, uint2& lval) {
    __nv_bfloat16 hx = __float2bfloat16(v.x), hy = __float2bfloat16(v.y);
    __nv_bfloat16 hz = __float2bfloat16(v.z), hw = __float2bfloat16(v.w);
    __nv_bfloat16 lx = __float2bfloat16(v.x - __bfloat162float(hx));
    __nv_bfloat16 ly = __float2bfloat16(v.y - __bfloat162float(hy));
    __nv_bfloat16 lz = __float2bfloat16(v.z - __bfloat162float(hz));
    __nv_bfloat16 lw = __float2bfloat16(v.w - __bfloat162float(hw));
    __nv_bfloat162 h01 = {hx, hy}, h23 = {hz, hw};
    __nv_bfloat162 l01 = {lx, ly}, l23 = {lz, lw};
    hval.x = *(uint32_t*)&h01; hval.y = *(uint32_t*)&h23;
    lval.x = *(uint32_t*)&l01; lval.y = *(uint32_t*)&l23;
}

template <int K4>
__device__ __forceinline__ void dot4(float acc[8], const float* S, int srow,
                                     const float* __restrict__ Wrow) {
    const float4* w4 = (const float4*)Wrow;
#pragma unroll 4
    for (int d4 = 0; d4 < K4; d4++) {
        float4 w = w4[d4];
#pragma unroll
        for (int r = 0; r < 8; r++) {
            const float4 sv = *(const float4*)(S + r * srow + d4 * 4);
            acc[r] += sv.x * w.x + sv.y * w.y + sv.z * w.z + sv.w * w.w;
        }
    }
}

__device__ __forceinline__ void warp_ln_row(const float* src, float* dst,
                                            const float* __restrict__ w,
                                            const float* __restrict__ b, int lane) {
    float vals[8];
    float s = 0.f, s2 = 0.f;
#pragma unroll
    for (int k = 0; k < 8; k++) {
        float v = src[lane + 32 * k];
        vals[k] = v; s += v; s2 += v * v;
    }
    s = warp_sum(s); s2 = warp_sum(s2);
    float m = s * (1.0f / 256.0f);
    float rs = rsqrtf(s2 * (1.0f / 256.0f) - m * m + 1e-5f);
#pragma unroll
    for (int k = 0; k < 8; k++) {
        int d = lane + 32 * k;
        dst[d] = (vals[k] - m) * rs * w[d] + b[d];
    }
}

// ---------------- big LN over inputs (fp32 only) ----------------
__global__ void ln_apply_kernel(const float* __restrict__ x, float* __restrict__ y,
                                const float* __restrict__ w, const float* __restrict__ bb) {
    int row = blockIdx.x * 8 + threadIdx.y;
    int lane = threadIdx.x;
    warp_ln_row(x + (size_t)row * Dd, y + (size_t)row * Dd, w, bb, lane);
}

// ---------------- precompute: C[e][d] = Σ_j X[j][e]·Y[j][d]  (XᵀY) ----------------
__global__ __launch_bounds__(256) void atb_kernel(const float* __restrict__ X,
                                                  const float* __restrict__ Y,
                                                  float* __restrict__ C) {
    __shared__ float Xs[16][68];
    __shared__ float Ys[16][68];
    int e0 = blockIdx.x * 64, d0 = blockIdx.y * 64;
    int tid = threadIdx.x;
    int row_t = tid >> 4, col_t = tid & 15;
    int jr = tid >> 4, c4 = (tid & 15) << 2;
    float acc[4][4];
#pragma unroll
    for (int i = 0; i < 4; i++)
#pragma unroll
        for (int j = 0; j < 4; j++) acc[i][j] = 0.f;
    for (int jb = 0; jb < 256; jb += 16) {
        float4 xv = *(const float4*)(X + (size_t)(jb + jr) * Dd + e0 + c4);
        Xs[jr][c4 + 0] = xv.x; Xs[jr][c4 + 1] = xv.y;
        Xs[jr][c4 + 2] = xv.z; Xs[jr][c4 + 3] = xv.w;
        float4 yv = *(const float4*)(Y + (size_t)(jb + jr) * Dd + d0 + c4);
        Ys[jr][c4 + 0] = yv.x; Ys[jr][c4 + 1] = yv.y;
        Ys[jr][c4 + 2] = yv.z; Ys[jr][c4 + 3] = yv.w;
        __syncthreads();
#pragma unroll
        for (int k = 0; k < 16; k++)
#pragma unroll
            for (int i = 0; i < 4; i++)
#pragma unroll
                for (int j = 0; j < 4; j++)
                    acc[i][j] += Xs[k][row_t * 4 + i] * Ys[k][col_t * 4 + j];
        __syncthreads();
    }
#pragma unroll
    for (int i = 0; i < 4; i++)
#pragma unroll
        for (int j = 0; j < 4; j++)
            C[(size_t)(e0 + row_t * 4 + i) * Dd + d0 + col_t * 4 + j] = acc[i][j];
}

// ---------------- precompute: C[g][e] = Σ_d A[g][d]·B[d][e]  (A·B) ----------------
__global__ __launch_bounds__(256) void ab_kernel(const float* __restrict__ A,
                                                 const float* __restrict__ B,
                                                 float* __restrict__ C) {
    __shared__ float As[16][68];
    __shared__ float Bs[16][68];
    int g0 = blockIdx.x * 64, e0 = blockIdx.y * 64;
    int tid = threadIdx.x;
    int row_t = tid >> 4, col_t = tid & 15;
    int r = tid >> 2, k4 = (tid & 3) << 2;
    int jr = tid >> 4, c4 = (tid & 15) << 2;
    float acc[4][4];
#pragma unroll
    for (int i = 0; i < 4; i++)
#pragma unroll
        for (int j = 0; j < 4; j++) acc[i][j] = 0.f;
    for (int db = 0; db < 256; db += 16) {
        float4 av = *(const float4*)(A + (size_t)(g0 + r) * Dd + db + k4);
        As[k4 + 0][r] = av.x; As[k4 + 1][r] = av.y;
        As[k4 + 2][r] = av.z; As[k4 + 3][r] = av.w;
        float4 bv = *(const float4*)(B + (size_t)(db + jr) * Dd + e0 + c4);
        Bs[jr][c4 + 0] = bv.x; Bs[jr][c4 + 1] = bv.y;
        Bs[jr][c4 + 2] = bv.z; Bs[jr][c4 + 3] = bv.w;
        __syncthreads();
#pragma unroll
        for (int k = 0; k < 16; k++)
#pragma unroll
            for (int i = 0; i < 4; i++)
#pragma unroll
                for (int j = 0; j < 4; j++)
                    acc[i][j] += As[k][row_t * 4 + i] * Bs[k][col_t * 4 + j];
        __syncthreads();
    }
#pragma unroll
    for (int i = 0; i < 4; i++)
#pragma unroll
        for (int j = 0; j < 4; j++)
            C[(size_t)(g0 + row_t * 4 + i) * Dd + e0 + col_t * 4 + j] = acc[i][j];
}

// ---------------- slots init ----------------
__global__ void slots_init_kernel(const float* __restrict__ mu,
                                  const float* __restrict__ ls,
                                  const float* __restrict__ noise) {
    int i = blockIdx.x * 256 + threadIdx.x;
    int kd = i % (Kk * Dd);
    g_slots[i] = mu[kd] + __expf(ls[kd]) * noise[i];
}

// ---------------- ln_slots + q (before first iteration) ----------------
__global__ __launch_bounds__(256) void slot_lnq_kernel(const float* __restrict__ lns_w,
                                                       const float* __restrict__ lns_b) {
    __shared__ float a_s[8][256];
    int t = threadIdx.x, lane = t & 31, wid = t >> 5;
    int row0 = blockIdx.x * 8;
    warp_ln_row(g_slots + (size_t)(row0 + wid) * Dd, &a_s[wid][0], lns_w, lns_b, lane);
    __syncthreads();
    float qa[8] = {0, 0, 0, 0, 0, 0, 0, 0};
    dot4<64>(qa, &a_s[0][0], 256, g_wqk + (size_t)t * Dd);
#pragma unroll
    for (int r = 0; r < 8; r++) g_q[(size_t)(row0 + r) * Dd + t] = qa[r];
}

// ---------------- fused attention pass: HMMA phase 1 (on-the-fly bf16 split)
// grid (NCH, Bb), block 256 (8 warps; warp w owns n-rows w*16..w*16+15).
__global__ __launch_bounds__(256) void attn_pass_kernel(const float* __restrict__ q,
                                                        const float* __restrict__ xln,
                                                        float* __restrict__ attn_out,
                                                        int final_pass) {
    extern __shared__ char smc[];
    uint32_t sb = smem_u32(smc);
    float* as_ = (float*)(smc + SM_AS);
    int b = blockIdx.y, chunk = blockIdx.x, t = threadIdx.x;
    int wid = t >> 5, lane = t & 31;

    // stage q (fp32 → hi/lo bf16): 16 rows x 256 d (row 15 zero), stride QROW
    {
        const float4* q4p = (const float4*)(q + (size_t)b * Kk * Dd);
        float4 z4 = make_float4(0.f, 0.f, 0.f, 0.f);
#pragma unroll
        for (int i = t; i < 16 * 64; i += 256) {
            int row = i >> 6, grp = i & 63;            // grp: 4 d per float4
            float4 v = (row < Kk) ? q4p[row * 64 + grp] : z4;
            uint2 hv, lv;
            split4(v, hv, lv);
            int so = (row * QROW + grp * 4) * 2;
            *(uint2*)(smc + SM_QH + so) = hv;
            *(uint2*)(smc + SM_QL + so) = lv;
        }
    }

    int n_glob0 = chunk * CHN;
    int a_row = wid * 16 + (lane & 15);
    int a_koff = (lane >> 4) << 3;
    int b_row = (lane & 7) + ((lane >> 4) << 3);
    int b_koff = ((lane >> 3) & 1) << 3;

    float acc0[8], acc1[8];
#pragma unroll
    for (int i = 0; i < 8; i++) { acc0[i] = 0.f; acc1[i] = 0.f; }

    for (int c = 0; c < 4; c++) {                      // k-chunks of 64 d
        __syncthreads();
        // stage x̂ (fp32 → hi/lo): 128 rows x 64 d, stride SROW
        const float4* xg = (const float4*)(xln + ((size_t)b * Nn + n_glob0) * Dd + c * 64);
#pragma unroll
        for (int i = t; i < 128 * 16; i += 256) {
            int row = i >> 4, grp = i & 15;
            float4 v = xg[(size_t)row * 64 + grp];
            uint2 hv, lv;
            split4(v, hv, lv);
            int so = (row * SROW + grp * 4) * 2;
            *(uint2*)(smc + SM_XH + so) = hv;
            *(uint2*)(smc + SM_XL + so) = lv;
        }
        __syncthreads();
#pragma unroll
        for (int ks = 0; ks < 4; ks++) {
            int kk = ks * 16;
            uint32_t ah0, ah1, ah2, ah3, al0, al1, al2, al3;
            uint32_t aoff = (uint32_t)(a_row * SROW + kk + a_koff) * 2;
            ldsm_x4(ah0, ah1, ah2, ah3, sb + SM_XH + aoff);
            ldsm_x4(al0, al1, al2, al3, sb + SM_XL + aoff);
            uint32_t bh[4], bl[4];
            uint32_t boff = (uint32_t)(b_row * QROW + c * 64 + kk + b_koff) * 2;
            ldsm_x4(bh[0], bh[1], bh[2], bh[3], sb + SM_QH + boff);
            ldsm_x4(bl[0], bl[1], bl[2], bl[3], sb + SM_QL + boff);
            mma_bf16(acc0, ah0, ah1, ah2, ah3, bh[0], bh[1]);
            mma_bf16(acc0, ah0, ah1, ah2, ah3, bl[0], bl[1]);
            mma_bf16(acc0, al0, al1, al2, al3, bh[0], bh[1]);
            mma_bf16(acc1, ah0, ah1, ah2, ah3, bh[2], bh[3]);
            mma_bf16(acc1, ah0, ah1, ah2, ah3, bl[2], bl[3]);
            mma_bf16(acc1, al0, al1, al2, al3, bh[2], bh[3]);
        }
    }

    // softmax on fragments (R11-proven mapping)
    int c_ = lane & 3;
    bool mask15 = (c_ == 3);
#pragma unroll
    for (int half = 0; half < 2; half++) {
        float v0 = acc0[half * 2 + 0] * 0.0625f;
        float v1 = acc0[half * 2 + 1] * 0.0625f;
        float v2 = acc1[half * 2 + 0] * 0.0625f;
        float v3 = mask15 ? -1e30f : acc1[half * 2 + 1] * 0.0625f;
        float mx = fmaxf(fmaxf(v0, v1), fmaxf(v2, v3));
        mx = fmaxf(mx, __shfl_xor_sync(0xffffffffu, mx, 1));
        mx = fmaxf(mx, __shfl_xor_sync(0xffffffffu, mx, 2));
        v0 = __expf(v0 - mx); v1 = __expf(v1 - mx);
        v2 = __expf(v2 - mx); v3 = mask15 ? 0.f : __expf(v3 - mx);
        float sum = v0 + v1 + v2 + v3;
        sum += __shfl_xor_sync(0xffffffffu, sum, 1);
        sum += __shfl_xor_sync(0xffffffffu, sum, 2);
        float inv = 1.0f / sum;
        int n_loc = wid * 16 + (lane >> 2) + half * 8;
        as_[(2 * c_ + 0) * AS2 + n_loc] = v0 * inv;
        as_[(2 * c_ + 1) * AS2 + n_loc] = v1 * inv;
        as_[(8 + 2 * c_) * AS2 + n_loc] = v2 * inv;
        if (!mask15) as_[(9 + 2 * c_) * AS2 + n_loc] = v3 * inv;
    }
    __syncthreads();

    if (final_pass) {
        for (int i = t; i < Kk * CHN; i += 256) {
            int s = i >> 7, n = i & 127;
            attn_out[((size_t)(b * Kk + s)) * Nn + n_glob0 + n] = as_[s * AS2 + n];
        }
        return;
    }

    // partial rowsums (15 threads)
    if (t < Kk) {
        float ps = 0.f;
#pragma unroll 8
        for (int n = 0; n < CHN; n++) ps += as_[t * AS2 + n];
        g_part[(b * Kk + t) * NCH + chunk] = ps;
    }

    // phase 2 (fp32, L2-hot re-read of the same array): thread = d
    float acc[Kk];
#pragma unroll
    for (int s = 0; s < Kk; s++) acc[s] = 0.f;
    const float* xp = xln + ((size_t)b * Nn + n_glob0) * Dd + t;
#pragma unroll 2
    for (int n4 = 0; n4 < CHN / 4; n4++) {
        float x0 = xp[(4 * n4 + 0) * Dd];
        float x1 = xp[(4 * n4 + 1) * Dd];
        float x2 = xp[(4 * n4 + 2) * Dd];
        float x3 = xp[(4 * n4 + 3) * Dd];
#pragma unroll
        for (int s = 0; s < Kk; s++) {
            float4 a4 = *(const float4*)(as_ + s * AS2 + 4 * n4);
            acc[s] += a4.x * x0 + a4.y * x1 + a4.z * x2 + a4.w * x3;
        }
    }
#pragma unroll
    for (int s = 0; s < Kk; s++)
        g_updpart[((size_t)chunk * BK_TOT + b * Kk + s) * Dd + t] = acc[s];
}

// ---------------- fused slot update: U-reduce → GRU → MLP → LN → q ----------------
__global__ __launch_bounds__(256) void slot_update_kernel(
    const float* __restrict__ whh, const float* __restrict__ w1,
    const float* __restrict__ w2,
    const float* __restrict__ bih, const float* __restrict__ bhh,
    const float* __restrict__ b1, const float* __restrict__ b2,
    const float* __restrict__ lnm_w, const float* __restrict__ lnm_b,
    const float* __restrict__ lns_w, const float* __restrict__ lns_b) {
    __shared__ float u_s[8][256];
    __shared__ float h_s[8][256];
    __shared__ float a_s[8][256];
    __shared__ float h1_s[8][512];
    __shared__ float inv_s[8];
    int t = threadIdx.x, lane = t & 31, wid = t >> 5;
    int row0 = blockIdx.x * 8;

#pragma unroll
    for (int r = 0; r < 8; r++) h_s[r][t] = g_slots[(size_t)(row0 + r) * Dd + t];
    if (t < 8) {
        float s = 0.f;
#pragma unroll
        for (int c = 0; c < NCH; c++) s += g_part[(row0 + t) * NCH + c];
        inv_s[t] = 1.0f / (s + 1e-8f);
    }
    __syncthreads();
#pragma unroll
    for (int r = 0; r < 8; r++) {
        float a = 0.f;
#pragma unroll 8
        for (int c = 0; c < NCH; c++)
            a += g_updpart[((size_t)c * BK_TOT + row0 + r) * Dd + t];
        u_s[r][t] = a * inv_s[r];
    }
    __syncthreads();

    float ri[8] = {0}, rh[8] = {0}, zi[8] = {0}, zh[8] = {0}, ni[8] = {0}, nh[8] = {0};
    dot4<64>(ri, &u_s[0][0], 256, g_wiv + (size_t)t * Dd);
    dot4<64>(zi, &u_s[0][0], 256, g_wiv + (size_t)(256 + t) * Dd);
    dot4<64>(ni, &u_s[0][0], 256, g_wiv + (size_t)(512 + t) * Dd);
    dot4<64>(rh, &h_s[0][0], 256, whh + (size_t)t * Dd);
    dot4<64>(zh, &h_s[0][0], 256, whh + (size_t)(256 + t) * Dd);
    dot4<64>(nh, &h_s[0][0], 256, whh + (size_t)(512 + t) * Dd);
    float bir = bih[t], bhr = bhh[t];
    float biz = bih[256 + t], bhz = bhh[256 + t];
    float bin = bih[512 + t], bhn = bhh[512 + t];
    __syncthreads();
#pragma unroll
    for (int r = 0; r < 8; r++) {
        float rg = sigmoidf_(ri[r] + bir + rh[r] + bhr);
        float zg = sigmoidf_(zi[r] + biz + zh[r] + bhz);
        float ng = tanhf(ni[r] + bin + rg * (nh[r] + bhn));
        h_s[r][t] = (1.0f - zg) * ng + zg * h_s[r][t];
    }
    __syncthreads();
    warp_ln_row(&h_s[wid][0], &a_s[wid][0], lnm_w, lnm_b, lane);
    __syncthreads();
    float m0[8] = {0}, m1[8] = {0};
    dot4<64>(m0, &a_s[0][0], 256, w1 + (size_t)t * Dd);
    dot4<64>(m1, &a_s[0][0], 256, w1 + (size_t)(256 + t) * Dd);
    float b1a = b1[t], b1b = b1[256 + t];
#pragma unroll
    for (int r = 0; r < 8; r++) {
        h1_s[r][t] = fmaxf(m0[r] + b1a, 0.f);
        h1_s[r][256 + t] = fmaxf(m1[r] + b1b, 0.f);
    }
    __syncthreads();
    float m2[8] = {0};
    dot4<128>(m2, &h1_s[0][0], 512, w2 + (size_t)t * Hh);
    float b2t = b2[t];
#pragma unroll
    for (int r = 0; r < 8; r++) {
        float ns = h_s[r][t] + m2[r] + b2t;
        g_slots[(size_t)(row0 + r) * Dd + t] = ns;
        a_s[r][t] = ns;
    }
    __syncthreads();
    warp_ln_row(&a_s[wid][0], &u_s[wid][0], lns_w, lns_b, lane);
    __syncthreads();
    float qa[8] = {0};
    dot4<64>(qa, &u_s[0][0], 256, g_wqk + (size_t)t * Dd);
#pragma unroll
    for (int r = 0; r < 8; r++) g_q[(size_t)(row0 + r) * Dd + t] = qa[r];
}

__global__ void copy_kernel(const float* __restrict__ src, float* __restrict__ dst, int n) {
    int i = blockIdx.x * 256 + threadIdx.x;
    if (i < n) dst[i] = src[i];
}

// ---------------- host orchestration ----------------
extern "C" void kernel_launch(void* const* d_in, const int* in_sizes, int n_in,
                              void* d_out, int out_size) {
    const float* inputs        = (const float*)d_in[0];
    const float* slot_noise    = (const float*)d_in[1];
    const float* slots_mu      = (const float*)d_in[2];
    const float* slots_logsig  = (const float*)d_in[3];
    const float* Wq            = (const float*)d_in[4];
    const float* Wk            = (const float*)d_in[5];
    const float* Wv            = (const float*)d_in[6];
    const float* w_ih          = (const float*)d_in[7];
    const float* w_hh          = (const float*)d_in[8];
    const float* b_ih          = (const float*)d_in[9];
    const float* b_hh          = (const float*)d_in[10];
    const float* mlp_w1        = (const float*)d_in[11];
    const float* mlp_b1        = (const float*)d_in[12];
    const float* mlp_w2        = (const float*)d_in[13];
    const float* mlp_b2        = (const float*)d_in[14];
    const float* ln_in_w       = (const float*)d_in[15];
    const float* ln_in_b       = (const float*)d_in[16];
    const float* ln_s_w        = (const float*)d_in[17];
    const float* ln_s_b        = (const float*)d_in[18];
    const float* ln_m_w        = (const float*)d_in[19];
    const float* ln_m_b        = (const float*)d_in[20];
    float* out = (float*)d_out;

    float *p_xln, *p_wqk, *p_wiv, *p_q, *p_slots;
    cudaGetSymbolAddress((void**)&p_xln, g_xln);
    cudaGetSymbolAddress((void**)&p_wqk, g_wqk);
    cudaGetSymbolAddress((void**)&p_wiv, g_wiv);
    cudaGetSymbolAddress((void**)&p_q, g_q);
    cudaGetSymbolAddress((void**)&p_slots, g_slots);

    cudaFuncSetAttribute(attn_pass_kernel,
                         cudaFuncAttributeMaxDynamicSharedMemorySize, SM_BYTES);

    ln_apply_kernel<<<BN_TOT / 8, dim3(32, 8)>>>(inputs, p_xln, ln_in_w, ln_in_b);
    atb_kernel<<<dim3(4, 4), 256>>>(Wk, Wq, p_wqk);
    ab_kernel<<<dim3(12, 4), 256>>>(w_ih, Wv, p_wiv);
    slots_init_kernel<<<BK_TOT, 256>>>(slots_mu, slots_logsig, slot_noise);
    slot_lnq_kernel<<<120, 256>>>(ln_s_w, ln_s_b);

    for (int it = 0; it < 3; it++) {
        attn_pass_kernel<<<dim3(NCH, Bb), 256, SM_BYTES>>>(p_q, p_xln, nullptr, 0);
        slot_update_kernel<<<120, 256>>>(w_hh, mlp_w1, mlp_w2, b_ih, b_hh,
                                         mlp_b1, mlp_b2, ln_m_w, ln_m_b, ln_s_w, ln_s_b);
    }

    attn_pass_kernel<<<dim3(NCH, Bb), 256, SM_BYTES>>>(p_q, p_xln, out + BK_TOT * Dd, 1);
    copy_kernel<<<960, 256>>>(p_slots, out, BK_TOT * Dd);
}

// round 17
// speedup vs baseline: 1.0741x; 1.0741x over previous
#include <cuda_runtime.h>
#include <cuda_bf16.h>
#include <math.h>
#include <stdint.h>

// SlotAttention GB300 — Round 16: R14 (best) + phase-2 updates on HMMA.
// A = attn bf16 hi/lo (written at softmax), B = x̂ tiles via ldmatrix.trans.
// Phase 1 & slot chain identical to R14.

#define Bb 64
#define Nn 4096
#define Dd 256
#define Kk 15
#define Hh 512
#define BN_TOT (Bb * Nn)   // 262144
#define BK_TOT (Bb * Kk)   // 960
#define NCH 32             // n-chunks per batch
#define CHN 128            // n per chunk (HMMA tile M)
#define SROW 72            // x̂ smem row stride (bf16)
#define QROW 264           // q smem row stride (bf16)
#define AS2 132            // attn smem row stride (floats)
#define ATR 136            // attn bf16 smem row stride (bf16)

// dynamic smem byte offsets for attn_pass
#define SM_XH 0
#define SM_XL 18432
#define SM_QH 36864
#define SM_QL 45312
#define SM_AS 53760
#define SM_AH2 62208
#define SM_AL2 66560
#define SM_BYTES 70912

// ---------------- scratch ----------------
__device__ float g_xln[(size_t)BN_TOT * Dd];      // 256 MiB (ONLY x̂ copy)
__device__ float g_wqk[Dd * Dd];
__device__ float g_wiv[3 * Dd * Dd];
__device__ float g_slots[BK_TOT * Dd];
__device__ float g_q[BK_TOT * Dd];
__device__ float g_part[BK_TOT * NCH];
__device__ float g_updpart[(size_t)NCH * BK_TOT * Dd];  // 31.5 MB

// ---------------- helpers ----------------
__device__ __forceinline__ float warp_sum(float v) {
#pragma unroll
    for (int o = 16; o > 0; o >>= 1) v += __shfl_xor_sync(0xffffffffu, v, o);
    return v;
}
__device__ __forceinline__ float sigmoidf_(float x) { return 1.0f / (1.0f + __expf(-x)); }

__device__ __forceinline__ uint32_t smem_u32(const void* p) {
    uint32_t a;
    asm("{ .reg .u64 t; cvta.to.shared.u64 t, %1; cvt.u32.u64 %0, t; }" : "=r"(a) : "l"(p));
    return a;
}
__device__ __forceinline__ void ldsm_x4(uint32_t& r0, uint32_t& r1, uint32_t& r2, uint32_t& r3,
                                        uint32_t addr) {
    asm volatile("ldmatrix.sync.aligned.m8n8.x4.shared.b16 {%0,%1,%2,%3}, [%4];"
                 : "=r"(r0), "=r"(r1), "=r"(r2), "=r"(r3) : "r"(addr));
}
__device__ __forceinline__ void ldsm_x2t(uint32_t& r0, uint32_t& r1, uint32_t addr) {
    asm volatile("ldmatrix.sync.aligned.m8n8.x2.trans.shared.b16 {%0,%1}, [%2];"
                 : "=r"(r0), "=r"(r1) : "r"(addr));
}
__device__ __forceinline__ void mma_bf16(float* c, uint32_t a0, uint32_t a1, uint32_t a2,
                                         uint32_t a3, uint32_t b0, uint32_t b1) {
    asm volatile(
        "mma.sync.aligned.m16n8k16.row.col.f32.bf16.bf16.f32 "
        "{%0,%1,%2,%3}, {%4,%5,%6,%7}, {%8,%9}, {%0,%1,%2,%3};"
        : "+f"(c[0]), "+f"(c[1]), "+f"(c[2]), "+f"(c[3])
        : "r"(a0), "r"(a1), "r"(a2), "r"(a3), "r"(b0), "r"(b1));
}

// split a float4 into packed hi (bf16x2 pair) and lo
__device__ __forceinline__ void split4(float4 v, uint2& hval, uint2& lval) {
    __nv_bfloat16 hx = __float2bfloat16(v.x), hy = __float2bfloat16(v.y);
    __nv_bfloat16 hz = __float2bfloat16(v.z), hw = __float2bfloat16(v.w);
    __nv_bfloat16 lx = __float2bfloat16(v.x - __bfloat162float(hx));
    __nv_bfloat16 ly = __float2bfloat16(v.y - __bfloat162float(hy));
    __nv_bfloat16 lz = __float2bfloat16(v.z - __bfloat162float(hz));
    __nv_bfloat16 lw = __float2bfloat16(v.w - __bfloat162float(hw));
    __nv_bfloat162 h01 = {hx, hy}, h23 = {hz, hw};
    __nv_bfloat162 l01 = {lx, ly}, l23 = {lz, lw};
    hval.x = *(uint32_t*)&h01; hval.y = *(uint32_t*)&h23;
    lval.x = *(uint32_t*)&l01; lval.y = *(uint32_t*)&l23;
}

template <int K4>
__device__ __forceinline__ void dot4(float acc[8], const float* S, int srow,
                                     const float* __restrict__ Wrow) {
    const float4* w4 = (const float4*)Wrow;
#pragma unroll 4
    for (int d4 = 0; d4 < K4; d4++) {
        float4 w = w4[d4];
#pragma unroll
        for (int r = 0; r < 8; r++) {
            const float4 sv = *(const float4*)(S + r * srow + d4 * 4);
            acc[r] += sv.x * w.x + sv.y * w.y + sv.z * w.z + sv.w * w.w;
        }
    }
}

__device__ __forceinline__ void warp_ln_row(const float* src, float* dst,
                                            const float* __restrict__ w,
                                            const float* __restrict__ b, int lane) {
    float vals[8];
    float s = 0.f, s2 = 0.f;
#pragma unroll
    for (int k = 0; k < 8; k++) {
        float v = src[lane + 32 * k];
        vals[k] = v; s += v; s2 += v * v;
    }
    s = warp_sum(s); s2 = warp_sum(s2);
    float m = s * (1.0f / 256.0f);
    float rs = rsqrtf(s2 * (1.0f / 256.0f) - m * m + 1e-5f);
#pragma unroll
    for (int k = 0; k < 8; k++) {
        int d = lane + 32 * k;
        dst[d] = (vals[k] - m) * rs * w[d] + b[d];
    }
}

// ---------------- big LN over inputs (fp32 only) ----------------
__global__ void ln_apply_kernel(const float* __restrict__ x, float* __restrict__ y,
                                const float* __restrict__ w, const float* __restrict__ bb) {
    int row = blockIdx.x * 8 + threadIdx.y;
    int lane = threadIdx.x;
    warp_ln_row(x + (size_t)row * Dd, y + (size_t)row * Dd, w, bb, lane);
}

// ---------------- precompute: C[e][d] = Σ_j X[j][e]·Y[j][d]  (XᵀY) ----------------
__global__ __launch_bounds__(256) void atb_kernel(const float* __restrict__ X,
                                                  const float* __restrict__ Y,
                                                  float* __restrict__ C) {
    __shared__ float Xs[16][68];
    __shared__ float Ys[16][68];
    int e0 = blockIdx.x * 64, d0 = blockIdx.y * 64;
    int tid = threadIdx.x;
    int row_t = tid >> 4, col_t = tid & 15;
    int jr = tid >> 4, c4 = (tid & 15) << 2;
    float acc[4][4];
#pragma unroll
    for (int i = 0; i < 4; i++)
#pragma unroll
        for (int j = 0; j < 4; j++) acc[i][j] = 0.f;
    for (int jb = 0; jb < 256; jb += 16) {
        float4 xv = *(const float4*)(X + (size_t)(jb + jr) * Dd + e0 + c4);
        Xs[jr][c4 + 0] = xv.x; Xs[jr][c4 + 1] = xv.y;
        Xs[jr][c4 + 2] = xv.z; Xs[jr][c4 + 3] = xv.w;
        float4 yv = *(const float4*)(Y + (size_t)(jb + jr) * Dd + d0 + c4);
        Ys[jr][c4 + 0] = yv.x; Ys[jr][c4 + 1] = yv.y;
        Ys[jr][c4 + 2] = yv.z; Ys[jr][c4 + 3] = yv.w;
        __syncthreads();
#pragma unroll
        for (int k = 0; k < 16; k++)
#pragma unroll
            for (int i = 0; i < 4; i++)
#pragma unroll
                for (int j = 0; j < 4; j++)
                    acc[i][j] += Xs[k][row_t * 4 + i] * Ys[k][col_t * 4 + j];
        __syncthreads();
    }
#pragma unroll
    for (int i = 0; i < 4; i++)
#pragma unroll
        for (int j = 0; j < 4; j++)
            C[(size_t)(e0 + row_t * 4 + i) * Dd + d0 + col_t * 4 + j] = acc[i][j];
}

// ---------------- precompute: C[g][e] = Σ_d A[g][d]·B[d][e]  (A·B) ----------------
__global__ __launch_bounds__(256) void ab_kernel(const float* __restrict__ A,
                                                 const float* __restrict__ B,
                                                 float* __restrict__ C) {
    __shared__ float As[16][68];
    __shared__ float Bs[16][68];
    int g0 = blockIdx.x * 64, e0 = blockIdx.y * 64;
    int tid = threadIdx.x;
    int row_t = tid >> 4, col_t = tid & 15;
    int r = tid >> 2, k4 = (tid & 3) << 2;
    int jr = tid >> 4, c4 = (tid & 15) << 2;
    float acc[4][4];
#pragma unroll
    for (int i = 0; i < 4; i++)
#pragma unroll
        for (int j = 0; j < 4; j++) acc[i][j] = 0.f;
    for (int db = 0; db < 256; db += 16) {
        float4 av = *(const float4*)(A + (size_t)(g0 + r) * Dd + db + k4);
        As[k4 + 0][r] = av.x; As[k4 + 1][r] = av.y;
        As[k4 + 2][r] = av.z; As[k4 + 3][r] = av.w;
        float4 bv = *(const float4*)(B + (size_t)(db + jr) * Dd + e0 + c4);
        Bs[jr][c4 + 0] = bv.x; Bs[jr][c4 + 1] = bv.y;
        Bs[jr][c4 + 2] = bv.z; Bs[jr][c4 + 3] = bv.w;
        __syncthreads();
#pragma unroll
        for (int k = 0; k < 16; k++)
#pragma unroll
            for (int i = 0; i < 4; i++)
#pragma unroll
                for (int j = 0; j < 4; j++)
                    acc[i][j] += As[k][row_t * 4 + i] * Bs[k][col_t * 4 + j];
        __syncthreads();
    }
#pragma unroll
    for (int i = 0; i < 4; i++)
#pragma unroll
        for (int j = 0; j < 4; j++)
            C[(size_t)(g0 + row_t * 4 + i) * Dd + e0 + col_t * 4 + j] = acc[i][j];
}

// ---------------- slots init ----------------
__global__ void slots_init_kernel(const float* __restrict__ mu,
                                  const float* __restrict__ ls,
                                  const float* __restrict__ noise) {
    int i = blockIdx.x * 256 + threadIdx.x;
    int kd = i % (Kk * Dd);
    g_slots[i] = mu[kd] + __expf(ls[kd]) * noise[i];
}

// ---------------- ln_slots + q (before first iteration) ----------------
__global__ __launch_bounds__(256) void slot_lnq_kernel(const float* __restrict__ lns_w,
                                                       const float* __restrict__ lns_b) {
    __shared__ float a_s[8][256];
    int t = threadIdx.x, lane = t & 31, wid = t >> 5;
    int row0 = blockIdx.x * 8;
    warp_ln_row(g_slots + (size_t)(row0 + wid) * Dd, &a_s[wid][0], lns_w, lns_b, lane);
    __syncthreads();
    float qa[8] = {0, 0, 0, 0, 0, 0, 0, 0};
    dot4<64>(qa, &a_s[0][0], 256, g_wqk + (size_t)t * Dd);
#pragma unroll
    for (int r = 0; r < 8; r++) g_q[(size_t)(row0 + r) * Dd + t] = qa[r];
}

// ---------------- fused attention pass: HMMA both phases ----------------
// grid (NCH, Bb), block 256 (8 warps).
__global__ __launch_bounds__(256) void attn_pass_kernel(const float* __restrict__ q,
                                                        const float* __restrict__ xln,
                                                        float* __restrict__ attn_out,
                                                        int final_pass) {
    extern __shared__ char smc[];
    uint32_t sb = smem_u32(smc);
    float* as_ = (float*)(smc + SM_AS);
    __nv_bfloat16* ah2 = (__nv_bfloat16*)(smc + SM_AH2);
    __nv_bfloat16* al2 = (__nv_bfloat16*)(smc + SM_AL2);
    int b = blockIdx.y, chunk = blockIdx.x, t = threadIdx.x;
    int wid = t >> 5, lane = t & 31;

    // stage q (fp32 → hi/lo bf16): 16 rows x 256 d (row 15 zero), stride QROW
    {
        const float4* q4p = (const float4*)(q + (size_t)b * Kk * Dd);
        float4 z4 = make_float4(0.f, 0.f, 0.f, 0.f);
#pragma unroll
        for (int i = t; i < 16 * 64; i += 256) {
            int row = i >> 6, grp = i & 63;
            float4 v = (row < Kk) ? q4p[row * 64 + grp] : z4;
            uint2 hv, lv;
            split4(v, hv, lv);
            int so = (row * QROW + grp * 4) * 2;
            *(uint2*)(smc + SM_QH + so) = hv;
            *(uint2*)(smc + SM_QL + so) = lv;
        }
    }

    int n_glob0 = chunk * CHN;
    int a_row = wid * 16 + (lane & 15);
    int a_koff = (lane >> 4) << 3;
    int b_row = (lane & 7) + ((lane >> 4) << 3);
    int b_koff = ((lane >> 3) & 1) << 3;

    float acc0[8], acc1[8];
#pragma unroll
    for (int i = 0; i < 8; i++) { acc0[i] = 0.f; acc1[i] = 0.f; }

    for (int c = 0; c < 4; c++) {                      // phase-1 k-chunks of 64 d
        __syncthreads();
        const float4* xg = (const float4*)(xln + ((size_t)b * Nn + n_glob0) * Dd + c * 64);
#pragma unroll
        for (int i = t; i < 128 * 16; i += 256) {
            int row = i >> 4, grp = i & 15;
            float4 v = xg[(size_t)row * 64 + grp];
            uint2 hv, lv;
            split4(v, hv, lv);
            int so = (row * SROW + grp * 4) * 2;
            *(uint2*)(smc + SM_XH + so) = hv;
            *(uint2*)(smc + SM_XL + so) = lv;
        }
        __syncthreads();
#pragma unroll
        for (int ks = 0; ks < 4; ks++) {
            int kk = ks * 16;
            uint32_t ah0, ah1, ah2r, ah3, al0, al1, al2r, al3;
            uint32_t aoff = (uint32_t)(a_row * SROW + kk + a_koff) * 2;
            ldsm_x4(ah0, ah1, ah2r, ah3, sb + SM_XH + aoff);
            ldsm_x4(al0, al1, al2r, al3, sb + SM_XL + aoff);
            uint32_t bh[4], bl[4];
            uint32_t boff = (uint32_t)(b_row * QROW + c * 64 + kk + b_koff) * 2;
            ldsm_x4(bh[0], bh[1], bh[2], bh[3], sb + SM_QH + boff);
            ldsm_x4(bl[0], bl[1], bl[2], bl[3], sb + SM_QL + boff);
            mma_bf16(acc0, ah0, ah1, ah2r, ah3, bh[0], bh[1]);
            mma_bf16(acc0, ah0, ah1, ah2r, ah3, bl[0], bl[1]);
            mma_bf16(acc0, al0, al1, al2r, al3, bh[0], bh[1]);
            mma_bf16(acc1, ah0, ah1, ah2r, ah3, bh[2], bh[3]);
            mma_bf16(acc1, ah0, ah1, ah2r, ah3, bl[2], bl[3]);
            mma_bf16(acc1, al0, al1, al2r, al3, bh[2], bh[3]);
        }
    }

    // softmax on fragments; write fp32 as_ AND bf16 hi/lo attn (for phase-2 A)
    int c_ = lane & 3;
    bool mask15 = (c_ == 3);
#pragma unroll
    for (int half = 0; half < 2; half++) {
        float v0 = acc0[half * 2 + 0] * 0.0625f;
        float v1 = acc0[half * 2 + 1] * 0.0625f;
        float v2 = acc1[half * 2 + 0] * 0.0625f;
        float v3 = mask15 ? -1e30f : acc1[half * 2 + 1] * 0.0625f;
        float mx = fmaxf(fmaxf(v0, v1), fmaxf(v2, v3));
        mx = fmaxf(mx, __shfl_xor_sync(0xffffffffu, mx, 1));
        mx = fmaxf(mx, __shfl_xor_sync(0xffffffffu, mx, 2));
        v0 = __expf(v0 - mx); v1 = __expf(v1 - mx);
        v2 = __expf(v2 - mx); v3 = mask15 ? 0.f : __expf(v3 - mx);
        float sum = v0 + v1 + v2 + v3;
        sum += __shfl_xor_sync(0xffffffffu, sum, 1);
        sum += __shfl_xor_sync(0xffffffffu, sum, 2);
        float inv = 1.0f / sum;
        int n_loc = wid * 16 + (lane >> 2) + half * 8;
        float a0v = v0 * inv, a1v = v1 * inv, a2v = v2 * inv, a3v = v3 * inv;
        as_[(2 * c_ + 0) * AS2 + n_loc] = a0v;
        as_[(2 * c_ + 1) * AS2 + n_loc] = a1v;
        as_[(8 + 2 * c_) * AS2 + n_loc] = a2v;
        if (!mask15) as_[(9 + 2 * c_) * AS2 + n_loc] = a3v;
        // bf16 hi/lo for phase-2 A operand
        float vv[4] = {a0v, a1v, a2v, a3v};
        int sr[4] = {2 * c_, 2 * c_ + 1, 8 + 2 * c_, 9 + 2 * c_};
#pragma unroll
        for (int j = 0; j < 4; j++) {
            if (j == 3 && mask15) { ah2[15 * ATR + n_loc] = __float2bfloat16(0.f);
                                    al2[15 * ATR + n_loc] = __float2bfloat16(0.f); continue; }
            __nv_bfloat16 h = __float2bfloat16(vv[j]);
            ah2[sr[j] * ATR + n_loc] = h;
            al2[sr[j] * ATR + n_loc] = __float2bfloat16(vv[j] - __bfloat162float(h));
        }
    }
    __syncthreads();

    if (final_pass) {
        for (int i = t; i < Kk * CHN; i += 256) {
            int s = i >> 7, n = i & 127;
            attn_out[((size_t)(b * Kk + s)) * Nn + n_glob0 + n] = as_[s * AS2 + n];
        }
        return;
    }

    // partial rowsums (15 threads)
    if (t < Kk) {
        float ps = 0.f;
#pragma unroll 8
        for (int n = 0; n < CHN; n++) ps += as_[t * AS2 + n];
        g_part[(b * Kk + t) * NCH + chunk] = ps;
    }

    // phase 2 (HMMA): U[s][d] = Σ_n attn[s][n]·x̂[n][d]
    // per d-chunk c: re-stage x̂ hi/lo (L2-hot), warp wid owns d-tile wid*8.
    {
        int s_row = lane & 15;
        int akoff2 = (lane >> 4) << 3;
        for (int c = 0; c < 4; c++) {
            __syncthreads();
            const float4* xg = (const float4*)(xln + ((size_t)b * Nn + n_glob0) * Dd + c * 64);
#pragma unroll
            for (int i = t; i < 128 * 16; i += 256) {
                int row = i >> 4, grp = i & 15;
                float4 v = xg[(size_t)row * 64 + grp];
                uint2 hv, lv;
                split4(v, hv, lv);
                int so = (row * SROW + grp * 4) * 2;
                *(uint2*)(smc + SM_XH + so) = hv;
                *(uint2*)(smc + SM_XL + so) = lv;
            }
            __syncthreads();
            float uacc[4] = {0.f, 0.f, 0.f, 0.f};
#pragma unroll
            for (int ks = 0; ks < 8; ks++) {
                uint32_t Ah0, Ah1, Ah2, Ah3, Al0, Al1, Al2, Al3;
                uint32_t aoff = (uint32_t)(s_row * ATR + ks * 16 + akoff2) * 2;
                ldsm_x4(Ah0, Ah1, Ah2, Ah3, sb + SM_AH2 + aoff);
                ldsm_x4(Al0, Al1, Al2, Al3, sb + SM_AL2 + aoff);
                uint32_t Bh0, Bh1, Bl0, Bl1;
                uint32_t boff = (uint32_t)((ks * 16 + (lane & 15)) * SROW + wid * 8) * 2;
                ldsm_x2t(Bh0, Bh1, sb + SM_XH + boff);
                ldsm_x2t(Bl0, Bl1, sb + SM_XL + boff);
                mma_bf16(uacc, Ah0, Ah1, Ah2, Ah3, Bh0, Bh1);
                mma_bf16(uacc, Ah0, Ah1, Ah2, Ah3, Bl0, Bl1);
                mma_bf16(uacc, Al0, Al1, Al2, Al3, Bh0, Bh1);
            }
            int s0 = lane >> 2;
            int dg = c * 64 + wid * 8 + (lane & 3) * 2;
            float* up = g_updpart + ((size_t)chunk * BK_TOT + b * Kk) * Dd;
            *(float2*)(up + (size_t)s0 * Dd + dg) = make_float2(uacc[0], uacc[1]);
            if (s0 + 8 < Kk)
                *(float2*)(up + (size_t)(s0 + 8) * Dd + dg) = make_float2(uacc[2], uacc[3]);
        }
    }
}

// ---------------- fused slot update: U-reduce → GRU → MLP → LN → q ----------------
__global__ __launch_bounds__(256) void slot_update_kernel(
    const float* __restrict__ whh, const float* __restrict__ w1,
    const float* __restrict__ w2,
    const float* __restrict__ bih, const float* __restrict__ bhh,
    const float* __restrict__ b1, const float* __restrict__ b2,
    const float* __restrict__ lnm_w, const float* __restrict__ lnm_b,
    const float* __restrict__ lns_w, const float* __restrict__ lns_b) {
    __shared__ float u_s[8][256];
    __shared__ float h_s[8][256];
    __shared__ float a_s[8][256];
    __shared__ float h1_s[8][512];
    __shared__ float inv_s[8];
    int t = threadIdx.x, lane = t & 31, wid = t >> 5;
    int row0 = blockIdx.x * 8;

#pragma unroll
    for (int r = 0; r < 8; r++) h_s[r][t] = g_slots[(size_t)(row0 + r) * Dd + t];
    if (t < 8) {
        float s = 0.f;
#pragma unroll
        for (int c = 0; c < NCH; c++) s += g_part[(row0 + t) * NCH + c];
        inv_s[t] = 1.0f / (s + 1e-8f);
    }
    __syncthreads();
#pragma unroll
    for (int r = 0; r < 8; r++) {
        float a = 0.f;
#pragma unroll 8
        for (int c = 0; c < NCH; c++)
            a += g_updpart[((size_t)c * BK_TOT + row0 + r) * Dd + t];
        u_s[r][t] = a * inv_s[r];
    }
    __syncthreads();

    float ri[8] = {0}, rh[8] = {0}, zi[8] = {0}, zh[8] = {0}, ni[8] = {0}, nh[8] = {0};
    dot4<64>(ri, &u_s[0][0], 256, g_wiv + (size_t)t * Dd);
    dot4<64>(zi, &u_s[0][0], 256, g_wiv + (size_t)(256 + t) * Dd);
    dot4<64>(ni, &u_s[0][0], 256, g_wiv + (size_t)(512 + t) * Dd);
    dot4<64>(rh, &h_s[0][0], 256, whh + (size_t)t * Dd);
    dot4<64>(zh, &h_s[0][0], 256, whh + (size_t)(256 + t) * Dd);
    dot4<64>(nh, &h_s[0][0], 256, whh + (size_t)(512 + t) * Dd);
    float bir = bih[t], bhr = bhh[t];
    float biz = bih[256 + t], bhz = bhh[256 + t];
    float bin = bih[512 + t], bhn = bhh[512 + t];
    __syncthreads();
#pragma unroll
    for (int r = 0; r < 8; r++) {
        float rg = sigmoidf_(ri[r] + bir + rh[r] + bhr);
        float zg = sigmoidf_(zi[r] + biz + zh[r] + bhz);
        float ng = tanhf(ni[r] + bin + rg * (nh[r] + bhn));
        h_s[r][t] = (1.0f - zg) * ng + zg * h_s[r][t];
    }
    __syncthreads();
    warp_ln_row(&h_s[wid][0], &a_s[wid][0], lnm_w, lnm_b, lane);
    __syncthreads();
    float m0[8] = {0}, m1[8] = {0};
    dot4<64>(m0, &a_s[0][0], 256, w1 + (size_t)t * Dd);
    dot4<64>(m1, &a_s[0][0], 256, w1 + (size_t)(256 + t) * Dd);
    float b1a = b1[t], b1b = b1[256 + t];
#pragma unroll
    for (int r = 0; r < 8; r++) {
        h1_s[r][t] = fmaxf(m0[r] + b1a, 0.f);
        h1_s[r][256 + t] = fmaxf(m1[r] + b1b, 0.f);
    }
    __syncthreads();
    float m2[8] = {0};
    dot4<128>(m2, &h1_s[0][0], 512, w2 + (size_t)t * Hh);
    float b2t = b2[t];
#pragma unroll
    for (int r = 0; r < 8; r++) {
        float ns = h_s[r][t] + m2[r] + b2t;
        g_slots[(size_t)(row0 + r) * Dd + t] = ns;
        a_s[r][t] = ns;
    }
    __syncthreads();
    warp_ln_row(&a_s[wid][0], &u_s[wid][0], lns_w, lns_b, lane);
    __syncthreads();
    float qa[8] = {0};
    dot4<64>(qa, &u_s[0][0], 256, g_wqk + (size_t)t * Dd);
#pragma unroll
    for (int r = 0; r < 8; r++) g_q[(size_t)(row0 + r) * Dd + t] = qa[r];
}

__global__ void copy_kernel(const float* __restrict__ src, float* __restrict__ dst, int n) {
    int i = blockIdx.x * 256 + threadIdx.x;
    if (i < n) dst[i] = src[i];
}

// ---------------- host orchestration ----------------
extern "C" void kernel_launch(void* const* d_in, const int* in_sizes, int n_in,
                              void* d_out, int out_size) {
    const float* inputs        = (const float*)d_in[0];
    const float* slot_noise    = (const float*)d_in[1];
    const float* slots_mu      = (const float*)d_in[2];
    const float* slots_logsig  = (const float*)d_in[3];
    const float* Wq            = (const float*)d_in[4];
    const float* Wk            = (const float*)d_in[5];
    const float* Wv            = (const float*)d_in[6];
    const float* w_ih          = (const float*)d_in[7];
    const float* w_hh          = (const float*)d_in[8];
    const float* b_ih          = (const float*)d_in[9];
    const float* b_hh          = (const float*)d_in[10];
    const float* mlp_w1        = (const float*)d_in[11];
    const float* mlp_b1        = (const float*)d_in[12];
    const float* mlp_w2        = (const float*)d_in[13];
    const float* mlp_b2        = (const float*)d_in[14];
    const float* ln_in_w       = (const float*)d_in[15];
    const float* ln_in_b       = (const float*)d_in[16];
    const float* ln_s_w        = (const float*)d_in[17];
    const float* ln_s_b        = (const float*)d_in[18];
    const float* ln_m_w        = (const float*)d_in[19];
    const float* ln_m_b        = (const float*)d_in[20];
    float* out = (float*)d_out;

    float *p_xln, *p_wqk, *p_wiv, *p_q, *p_slots;
    cudaGetSymbolAddress((void**)&p_xln, g_xln);
    cudaGetSymbolAddress((void**)&p_wqk, g_wqk);
    cudaGetSymbolAddress((void**)&p_wiv, g_wiv);
    cudaGetSymbolAddress((void**)&p_q, g_q);
    cudaGetSymbolAddress((void**)&p_slots, g_slots);

    cudaFuncSetAttribute(attn_pass_kernel,
                         cudaFuncAttributeMaxDynamicSharedMemorySize, SM_BYTES);

    ln_apply_kernel<<<BN_TOT / 8, dim3(32, 8)>>>(inputs, p_xln, ln_in_w, ln_in_b);
    atb_kernel<<<dim3(4, 4), 256>>>(Wk, Wq, p_wqk);
    ab_kernel<<<dim3(12, 4), 256>>>(w_ih, Wv, p_wiv);
    slots_init_kernel<<<BK_TOT, 256>>>(slots_mu, slots_logsig, slot_noise);
    slot_lnq_kernel<<<120, 256>>>(ln_s_w, ln_s_b);

    for (int it = 0; it < 3; it++) {
        attn_pass_kernel<<<dim3(NCH, Bb), 256, SM_BYTES>>>(p_q, p_xln, nullptr, 0);
        slot_update_kernel<<<120, 256>>>(w_hh, mlp_w1, mlp_w2, b_ih, b_hh,
                                         mlp_b1, mlp_b2, ln_m_w, ln_m_b, ln_s_w, ln_s_b);
    }

    attn_pass_kernel<<<dim3(NCH, Bb), 256, SM_BYTES>>>(p_q, p_xln, out + BK_TOT * Dd, 1);
    copy_kernel<<<960, 256>>>(p_slots, out, BK_TOT * Dd);
}